// round 13
// baseline (speedup 1.0000x reference)
#include <cuda_runtime.h>
#include <cstdint>

// Gather 2048 columns (8 groups x 8 slices x 32 cols) from a [16384, 4096] f32
// matrix into d_out laid out as 8 concatenated [16384, 256] group blocks.
//
// R12 (noise-floor probe on the converged config): identical memory pattern
// to the optimal R2 kernel (one thread per float4, x4 front-batched LDG.128,
// 64B in flight per thread, contiguous STG.128), but 512-thread CTAs
// (grid 4096) instead of 256-thread (grid 8192): same resident warps/SM,
// half the block-dispatch events, coarser placement granularity.
//
// Converged state: 268 MB compulsory traffic @ ~5.9 TB/s sustained mixed
// R+W = ~45us harness floor. Falsified levers: evict hints (inert),
// cross-replay L2 pinning, single-wave persistence (occupancy cap),
// x8+256-bit composite (L1tex wavefront queue overfill).
//
// Index math (per float4 output index idx in [0, 2^23)):
//   g    = idx >> 20            (8 groups, 2^20 float4 each)
//   row  = (idx >> 6) & 16383   (64 float4 per output row)
//   c4   = idx & 63
//   in   = row*1024 + g*128 + (c4>>3)*16 + (c4&7)

__global__ void __launch_bounds__(512)
slice_cat_kernel(const float4* __restrict__ in4, float4* __restrict__ out4)
{
    const uint32_t base = blockIdx.x * 2048u + threadIdx.x;

    uint32_t in_idx[4];
#pragma unroll
    for (int k = 0; k < 4; ++k) {
        const uint32_t idx = base + k * 512u;
        const uint32_t g   = idx >> 20;
        const uint32_t row = (idx >> 6) & 16383u;
        const uint32_t c4  = idx & 63u;
        in_idx[k] = row * 1024u + g * 128u + (c4 >> 3) * 16u + (c4 & 7u);
    }

    float4 v[4];
#pragma unroll
    for (int k = 0; k < 4; ++k)
        v[k] = __ldg(&in4[in_idx[k]]);

#pragma unroll
    for (int k = 0; k < 4; ++k)
        out4[base + k * 512u] = v[k];
}

extern "C" void kernel_launch(void* const* d_in, const int* in_sizes, int n_in,
                              void* d_out, int out_size)
{
    (void)in_sizes; (void)n_in; (void)out_size;
    const float4* in4 = (const float4*)d_in[0];
    float4* out4 = (float4*)d_out;

    // total float4 = 2^23; 2048 per block -> 4096 blocks of 512 threads
    slice_cat_kernel<<<4096, 512>>>(in4, out4);
}

// round 14
// speedup vs baseline: 1.0014x; 1.0014x over previous
#include <cuda_runtime.h>
#include <cstdint>

// Gather 2048 columns (8 groups x 8 slices x 32 cols) from a [16384, 4096] f32
// matrix into d_out laid out as 8 concatenated [16384, 256] group blocks.
//
// FINAL — converged at the sustained mixed R+W DRAM roofline.
// 268 MB compulsory traffic per invocation @ ~5.9 TB/s sustained -> ~45us.
//
// Configuration (best measured across 13 rounds, = R2): one thread per
// float4, x4 unrolled with front-batched independent LDG.128s (64B in
// flight per thread — the measured sweet spot), 8192 blocks x 256 threads
// (~8 resident CTAs/SM = 64 warps/SM sustaining SM-wide memory-level
// parallelism). Stores perfectly contiguous STG.128 per warp-instruction;
// loads are 128B-aligned full-sector chunks (zero over-fetch).
//
// Levers tested and resolved (R1-R12):
//   - MLP unroll: helps to x4, saturates; x8 harness-neutral
//   - 256-bit accesses: neutral alone; regression with x8 (L1tex wavefront
//     queue overfill: 16 lines/warp-instr x 8 batched)
//   - L2 evict hints: inert without cudaAccessPolicyWindow (falsified 2x)
//   - cross-replay L2 pinning of input subset: null
//   - single-wave persistent grid: regression (28 warps/SM caps outstanding
//     loads; occupancy IS the bandwidth engine on GB300)
//   - CTA shape (512 threads): null
//   - TMA: no headroom by construction (LTS cap path-independent)
//
// Index math (per float4 output index idx in [0, 2^23)):
//   g    = idx >> 20            (8 groups, 2^20 float4 each)
//   row  = (idx >> 6) & 16383   (64 float4 per output row)
//   c4   = idx & 63
//   in   = row*1024 + g*128 + (c4>>3)*16 + (c4&7)

__global__ void __launch_bounds__(256)
slice_cat_kernel(const float4* __restrict__ in4, float4* __restrict__ out4)
{
    const uint32_t base = blockIdx.x * 1024u + threadIdx.x;

    uint32_t in_idx[4];
#pragma unroll
    for (int k = 0; k < 4; ++k) {
        const uint32_t idx = base + k * 256u;
        const uint32_t g   = idx >> 20;
        const uint32_t row = (idx >> 6) & 16383u;
        const uint32_t c4  = idx & 63u;
        in_idx[k] = row * 1024u + g * 128u + (c4 >> 3) * 16u + (c4 & 7u);
    }

    float4 v[4];
#pragma unroll
    for (int k = 0; k < 4; ++k)
        v[k] = __ldg(&in4[in_idx[k]]);

#pragma unroll
    for (int k = 0; k < 4; ++k)
        out4[base + k * 256u] = v[k];
}

extern "C" void kernel_launch(void* const* d_in, const int* in_sizes, int n_in,
                              void* d_out, int out_size)
{
    (void)in_sizes; (void)n_in; (void)out_size;
    const float4* in4 = (const float4*)d_in[0];
    float4* out4 = (float4*)d_out;

    // total float4 = 2^23; 1024 per block -> 8192 blocks
    slice_cat_kernel<<<8192, 256>>>(in4, out4);
}

// round 16
// speedup vs baseline: 1.0056x; 1.0042x over previous
#include <cuda_runtime.h>
#include <cstdint>

// Gather 2048 columns (8 groups x 8 slices x 32 cols) from a [16384, 4096] f32
// matrix into d_out laid out as 8 concatenated [16384, 256] group blocks.
//
// FINAL — converged at the sustained mixed R+W DRAM roofline.
// 268 MB compulsory traffic per invocation @ ~5.9 TB/s sustained -> ~45.4us
// harness steady-state (45.1-46.1 noise band over 6 repeat measurements).
//
// Configuration (best measured): one thread per float4, x4 unrolled with
// front-batched independent LDG.128s (64B in flight per thread — measured
// sweet spot), 8192 blocks x 256 threads (~8 resident CTAs/SM = 64 warps/SM
// sustaining SM-wide memory-level parallelism). Stores perfectly contiguous
// STG.128 per warp-instruction; loads 128B-aligned full-sector chunks
// (slices are 256B-aligned -> zero over-fetch).
//
// Levers tested and resolved (R1-R14):
//   - MLP unroll: helps to x4, saturates; x8 harness-neutral
//   - 256-bit accesses: neutral alone; regression with x8 (L1tex wavefront
//     queue overfill: 16 lines/warp-instr x 8 batched)
//   - L2 evict hints: inert without cudaAccessPolicyWindow (falsified 2x)
//   - cross-replay L2 pinning of input subset: null
//   - single-wave persistent grid: regression (28 warps/SM caps outstanding
//     loads; occupancy IS the bandwidth engine on GB300)
//   - CTA shape (512 threads): null
//   - TMA: no headroom by construction (LTS chip cap is path-independent)
//
// Index math (per float4 output index idx in [0, 2^23)):
//   g    = idx >> 20            (8 groups, 2^20 float4 each)
//   row  = (idx >> 6) & 16383   (64 float4 per output row)
//   c4   = idx & 63
//   in   = row*1024 + g*128 + (c4>>3)*16 + (c4&7)

__global__ void __launch_bounds__(256)
slice_cat_kernel(const float4* __restrict__ in4, float4* __restrict__ out4)
{
    const uint32_t base = blockIdx.x * 1024u + threadIdx.x;

    uint32_t in_idx[4];
#pragma unroll
    for (int k = 0; k < 4; ++k) {
        const uint32_t idx = base + k * 256u;
        const uint32_t g   = idx >> 20;
        const uint32_t row = (idx >> 6) & 16383u;
        const uint32_t c4  = idx & 63u;
        in_idx[k] = row * 1024u + g * 128u + (c4 >> 3) * 16u + (c4 & 7u);
    }

    float4 v[4];
#pragma unroll
    for (int k = 0; k < 4; ++k)
        v[k] = __ldg(&in4[in_idx[k]]);

#pragma unroll
    for (int k = 0; k < 4; ++k)
        out4[base + k * 256u] = v[k];
}

extern "C" void kernel_launch(void* const* d_in, const int* in_sizes, int n_in,
                              void* d_out, int out_size)
{
    (void)in_sizes; (void)n_in; (void)out_size;
    const float4* in4 = (const float4*)d_in[0];
    float4* out4 = (float4*)d_out;

    // total float4 = 2^23; 1024 per block -> 8192 blocks
    slice_cat_kernel<<<8192, 256>>>(in4, out4);
}